// round 2
// baseline (speedup 1.0000x reference)
#include <cuda_runtime.h>
#include <stdint.h>

#define BATCH   65536
#define HID     256
#define RNDS    64
#define FULLM   0xffffffffu
// 2x margin over worst-case half-ulp (2^-16 for |sum| < 512)
#define FLAG_T  3.0517578125e-5f

// ------------------------- static device scratch ---------------------------
__device__ uint32_t g_A [RNDS][256][8];   // (M != 0) bit rows
__device__ uint32_t g_Mp[RNDS][256][8];   // (M == +1)
__device__ uint32_t g_Mm[RNDS][256][8];   // (M == -1)
__device__ uint32_t g_P [2][32][256][8];  // tree ping-pong: linear part
__device__ uint32_t g_Q [2][32][256][8];  // tree ping-pong: affine part
__device__ uint32_t g_S [BATCH][8];       // packed state bits
__device__ uint32_t g_C [BATCH][8];       // packed floor(noise)&1 bits
__device__ uint32_t g_MT[512][8];         // columns of [P | Q]
__device__ uint32_t g_outw[BATCH][8];     // packed output bits
__device__ int      g_flagcnt;
__device__ int      g_flaglist[BATCH];

// ------------------------- kernel: reset flag counter ----------------------
__global__ void k_reset() { g_flagcnt = 0; }

// ------------------------- kernel: pack batch state + noise ----------------
// one warp per batch row; grid 8192 x 256  (65536 warps)
__global__ __launch_bounds__(256) void k_pack_state(
    const float* __restrict__ bits, const float* __restrict__ noise)
{
    int gw   = (blockIdx.x * 256 + threadIdx.x) >> 5;
    int lane = threadIdx.x & 31;
    int row  = gw;
    bool bad = false;
#pragma unroll
    for (int w = 0; w < 8; ++w) {
        float b = bits [(size_t)row * 256 + w * 32 + lane];
        float n = noise[(size_t)row * 256 + w * 32 + lane];
        uint32_t sw = __ballot_sync(FULLM, b > 0.5f);
        float fn = floorf(n);
        uint32_t cw = __ballot_sync(FULLM, (((int)fn) & 1) != 0);
        float d = ceilf(n) - n;
        bad = bad || (d > 0.0f && d < FLAG_T);
        if (lane == 0) { g_S[row][w] = sw; g_C[row][w] = cw; }
    }
    uint32_t anybad = __ballot_sync(FULLM, bad);
    if (lane == 0 && anybad) {
        int idx = atomicAdd(&g_flagcnt, 1);
        g_flaglist[idx] = row;
    }
}

// ------------------------- kernel: pack round matrices ---------------------
// one warp per matrix row; grid 2048 x 256 (16384 warps = 64*256 rows)
__global__ __launch_bounds__(256) void k_pack_masks(const float* __restrict__ mats)
{
    int gw   = (blockIdx.x * 256 + threadIdx.x) >> 5;
    int lane = threadIdx.x & 31;
    int r = gw >> 8, i = gw & 255;
    const float* rowp = mats + (size_t)gw * 256;
#pragma unroll
    for (int w = 0; w < 8; ++w) {
        float v = rowp[w * 32 + lane];
        uint32_t ap = __ballot_sync(FULLM, v != 0.0f);
        uint32_t mp = __ballot_sync(FULLM, v >  0.5f);
        uint32_t mm = __ballot_sync(FULLM, v < -0.5f);
        if (lane == 0) { g_A[r][i][w] = ap; g_Mp[r][i][w] = mp; g_Mm[r][i][w] = mm; }
    }
}

// ------------------------- GF(2) matmul core (shared by tree kernels) ------
// block: 256 threads, handles 32 output rows (rowblk) of C = H * B (+ extra).
// thread t: local row li = t>>3, k-slice ks = t&7 handles k == ks (mod 8).
__device__ __forceinline__ void gf2_block_matmul(
    const uint32_t (*H)[8], const uint32_t (*B)[8],
    const uint32_t (*ADD)[8],      // nullptr or row-wise XOR-in term
    uint32_t (*OUT)[8], int rowblk)
{
    __shared__ uint32_t Bs[256][8];
    __shared__ uint32_t Part[32][8][8];   // [li][ks][w]
    int t = threadIdx.x;
    for (int idx = t; idx < 2048; idx += 256)
        Bs[idx >> 3][idx & 7] = (&B[0][0])[idx];
    __syncthreads();

    int li = t >> 3, ks = t & 7;
    int i  = rowblk * 32 + li;
    uint32_t hw[8];
#pragma unroll
    for (int w = 0; w < 8; ++w) hw[w] = H[i][w];

    uint32_t acc[8] = {0,0,0,0,0,0,0,0};
#pragma unroll
    for (int wv = 0; wv < 8; ++wv) {
#pragma unroll
        for (int b2 = 0; b2 < 4; ++b2) {
            int bitpos = 8 * b2 + ks;
            uint32_t m = 0u - ((hw[wv] >> bitpos) & 1u);
            const uint32_t* Br = Bs[32 * wv + 8 * b2 + ks];
#pragma unroll
            for (int w = 0; w < 8; ++w) acc[w] ^= Br[w] & m;
        }
    }
#pragma unroll
    for (int w = 0; w < 8; ++w) Part[li][ks][w] = acc[w];
    __syncthreads();

    // reduce: thread t -> (li2 = t>>3, w = t&7)
    int li2 = t >> 3, w2 = t & 7;
    int i2  = rowblk * 32 + li2;
    uint32_t r = Part[li2][0][w2];
#pragma unroll
    for (int k2 = 1; k2 < 8; ++k2) r ^= Part[li2][k2][w2];
    if (ADD) r ^= ADD[i2][w2];
    OUT[i2][w2] = r;
}

// ------------------------- kernel: tree level 1 ----------------------------
// node n: P = A[2n+1]*A[2n], Q = A[2n+1] ^ I.  grid (32,1,8) x 256
__global__ __launch_bounds__(256) void k_compose_l1()
{
    int n = blockIdx.x, rb = blockIdx.z;
    gf2_block_matmul(g_A[2*n+1], g_A[2*n], nullptr, g_P[0][n], rb);
    // Q (trivial): thread t -> (li,w)
    int t = threadIdx.x;
    int li = t >> 3, w = t & 7;
    int i = rb * 32 + li;
    uint32_t q = g_A[2*n+1][i][w];
    if (w == (i >> 5)) q ^= 1u << (i & 31);
    g_Q[0][n][i][w] = q;
}

// ------------------------- kernel: generic tree level ----------------------
// grid (nodes, 2, 8) x 256.  y==0: P = Ph*Pl ; y==1: Q = Ph*Ql ^ Qh
__global__ __launch_bounds__(256) void k_compose_lv(int src, int dst)
{
    int n = blockIdx.x, isQ = blockIdx.y, rb = blockIdx.z;
    const uint32_t (*H)[8] = g_P[src][2*n+1];
    const uint32_t (*B)[8] = isQ ? g_Q[src][2*n] : g_P[src][2*n];
    const uint32_t (*ADD)[8] = isQ ? g_Q[src][2*n+1] : (const uint32_t (*)[8])nullptr;
    uint32_t (*OUT)[8] = isQ ? g_Q[dst][n] : g_P[dst][n];
    gf2_block_matmul(H, B, ADD, OUT, rb);
}

// ------------------------- kernel: transpose [P|Q] -> columns --------------
// final maps live in buffer 1, node 0.  one warp per column; grid 64 x 256
__global__ __launch_bounds__(256) void k_transpose()
{
    int j    = blockIdx.x * 8 + (threadIdx.x >> 5);  // 0..511
    int lane = threadIdx.x & 31;
    int jj = j & 255;
    const uint32_t (*src)[8] = (j < 256) ? g_P[1][0] : g_Q[1][0];
#pragma unroll
    for (int w = 0; w < 8; ++w) {
        uint32_t bit = (src[32 * w + lane][jj >> 5] >> (jj & 31)) & 1u;
        uint32_t col = __ballot_sync(FULLM, bit != 0);
        if (lane == 0) g_MT[j][w] = col;
    }
}

// ------------------------- kernel: batch apply (Four-Russians) -------------
// out_row = P*s ^ Q*c, 4-bit chunks, table per pass (P then Q). grid 256x256.
__global__ __launch_bounds__(256) void k_batch()
{
    __shared__ uint32_t T[64][16][9];   // 9-word pad: idx*9 mod 32 all-distinct
    int tid = threadIdx.x;
    int row = blockIdx.x * 256 + tid;
    uint32_t x[8], acc[8] = {0,0,0,0,0,0,0,0};
#pragma unroll
    for (int w = 0; w < 8; ++w) x[w] = g_S[row][w];

    int c = tid & 63, g = tid >> 6;     // this thread builds words 2g,2g+1 of chunk c
    for (int pass = 0; pass < 2; ++pass) {
        __syncthreads();
        uint32_t b0[4], b1[4];
#pragma unroll
        for (int j = 0; j < 4; ++j) {
            b0[j] = g_MT[pass * 256 + 4 * c + j][2 * g];
            b1[j] = g_MT[pass * 256 + 4 * c + j][2 * g + 1];
        }
        T[c][0][2 * g] = 0; T[c][0][2 * g + 1] = 0;
#pragma unroll
        for (int e = 1; e < 16; ++e) {
            int p = e & (e - 1);
            int j = __ffs(e) - 1;
            T[c][e][2 * g]     = T[c][p][2 * g]     ^ b0[j];
            T[c][e][2 * g + 1] = T[c][p][2 * g + 1] ^ b1[j];
        }
        __syncthreads();
#pragma unroll 8
        for (int cc = 0; cc < 64; ++cc) {
            uint32_t idx = (x[cc >> 3] >> ((cc & 7) * 4)) & 15u;
            const uint32_t* e = T[cc][idx];
#pragma unroll
            for (int w = 0; w < 8; ++w) acc[w] ^= e[w];
        }
        if (pass == 0) {
#pragma unroll
            for (int w = 0; w < 8; ++w) x[w] = g_C[row][w];
        }
    }
#pragma unroll
    for (int w = 0; w < 8; ++w) g_outw[row][w] = acc[w];
}

// ------------------------- kernel: unpack bits -> f32 ----------------------
__global__ void k_unpack(float* __restrict__ out)
{
    int row = blockIdx.x, i = threadIdx.x;
    uint32_t w = g_outw[row][i >> 5];
    out[(size_t)row * 256 + i] = (float)((w >> (i & 31)) & 1u);
}

// ------------------------- kernel: exact fallback for flagged rows ---------
// one warp per flagged row; state replicated in regs via ballot. grid 512x256
__global__ __launch_bounds__(256) void k_fixup(
    const float* __restrict__ bits, const float* __restrict__ noise,
    float* __restrict__ out)
{
    const int TOTW = 512 * 256 / 32;
    int gw   = (blockIdx.x * 256 + threadIdx.x) >> 5;
    int lane = threadIdx.x & 31;
    int nflag = g_flagcnt;
    for (int f = gw; f < nflag; f += TOTW) {
        int row = g_flaglist[f];
        uint32_t sw[8];
#pragma unroll
        for (int j = 0; j < 8; ++j)
            sw[j] = __ballot_sync(FULLM, bits[(size_t)row * 256 + 32 * j + lane] > 0.5f);
        for (int r = 0; r < RNDS; ++r) {
            uint32_t nb[8];
#pragma unroll
            for (int j = 0; j < 8; ++j) {
                int i = 32 * j + lane;
                int dot = 0;
#pragma unroll
                for (int w = 0; w < 8; ++w)
                    dot += __popc(g_Mp[r][i][w] & sw[w]) - __popc(g_Mm[r][i][w] & sw[w]);
                float v = floorf((float)dot + noise[(size_t)row * 256 + i]);
                nb[j] = __ballot_sync(FULLM, (((int)v) & 1) != 0);
            }
#pragma unroll
            for (int j = 0; j < 8; ++j) sw[j] = nb[j];
        }
#pragma unroll
        for (int j = 0; j < 8; ++j)
            out[(size_t)row * 256 + 32 * j + lane] = (float)((sw[j] >> lane) & 1u);
    }
}

// ------------------------- launch --------------------------------------------
extern "C" void kernel_launch(void* const* d_in, const int* in_sizes, int n_in,
                              void* d_out, int out_size)
{
    const float* bits  = (const float*)d_in[0];
    const float* noise = (const float*)d_in[1];
    const float* mats  = (const float*)d_in[2];
    float* out = (float*)d_out;

    k_reset<<<1, 1>>>();
    k_pack_state<<<8192, 256>>>(bits, noise);
    k_pack_masks<<<2048, 256>>>(mats);
    k_compose_l1<<<dim3(32, 1, 8), 256>>>();
    k_compose_lv<<<dim3(16, 2, 8), 256>>>(0, 1);
    k_compose_lv<<<dim3( 8, 2, 8), 256>>>(1, 0);
    k_compose_lv<<<dim3( 4, 2, 8), 256>>>(0, 1);
    k_compose_lv<<<dim3( 2, 2, 8), 256>>>(1, 0);
    k_compose_lv<<<dim3( 1, 2, 8), 256>>>(0, 1);
    k_transpose<<<64, 256>>>();
    k_batch<<<256, 256>>>();
    k_unpack<<<65536, 256>>>(out);
    k_fixup<<<512, 256>>>(bits, noise, out);
}